// round 1
// baseline (speedup 1.0000x reference)
#include <cuda_runtime.h>
#include <cuda_bf16.h>

// LBP uniform (P=8, R=1) over (B,C,H,W)=(32,3,512,512) float32.
// out = (trans<=2 ? popcount(bits) : 9) / 255
// bits[i] = quant(neighbor_i) >= quant(center), zero-padded borders.
//
// Strategy: one warp per (row, 128-col segment). Each lane loads float4 from
// top/center/bottom rows (3x LDG.128), halo columns via warp shuffle,
// writes one STG.128. Memory-bound; LSU traffic ~4 warp memops / 128 px.

#define IMG_W 512
#define IMG_H 512

__device__ __forceinline__ float quant8(float v) {
    // emulate uint8 quantization: clip(floor(v*255), 0, 255)
    return floorf(fminf(fmaxf(v * 255.0f, 0.0f), 255.0f));
}

__global__ __launch_bounds__(256)
void lbp_kernel(const float* __restrict__ x, float* __restrict__ out, int nrows) {
    const int warpG = blockIdx.x * (blockDim.x >> 5) + (threadIdx.x >> 5);
    const int lane  = threadIdx.x & 31;
    const int r = warpG >> 2;        // flattened row over B*C*H
    const int s = warpG & 3;         // which 128-col segment
    if (r >= nrows) return;

    const int h = r & (IMG_H - 1);   // row within image
    const bool hasTop = (h != 0);
    const bool hasBot = (h != IMG_H - 1);

    const float* rowc = x + (size_t)r * IMG_W + s * 128;
    const float* rowt = rowc - IMG_W;
    const float* rowb = rowc + IMG_W;
    const int col = lane * 4;

    const float4 z4 = make_float4(0.f, 0.f, 0.f, 0.f);
    float4 c4 = *reinterpret_cast<const float4*>(rowc + col);
    float4 t4 = hasTop ? *reinterpret_cast<const float4*>(rowt + col) : z4;
    float4 b4 = hasBot ? *reinterpret_cast<const float4*>(rowb + col) : z4;

    // quantized values, indices 0..3 within this lane's 4 pixels
    float qc[6], qt[6], qb[6];  // [0]=left halo (col-1), [1..4]=cols, [5]=right halo (col+4)
    qc[1] = quant8(c4.x); qc[2] = quant8(c4.y); qc[3] = quant8(c4.z); qc[4] = quant8(c4.w);
    qt[1] = quant8(t4.x); qt[2] = quant8(t4.y); qt[3] = quant8(t4.z); qt[4] = quant8(t4.w);
    qb[1] = quant8(b4.x); qb[2] = quant8(b4.y); qb[3] = quant8(b4.z); qb[4] = quant8(b4.w);

    // halo via shuffle: left comes from lane-1's [4], right from lane+1's [1]
    qc[0] = __shfl_up_sync(0xFFFFFFFFu, qc[4], 1);
    qt[0] = __shfl_up_sync(0xFFFFFFFFu, qt[4], 1);
    qb[0] = __shfl_up_sync(0xFFFFFFFFu, qb[4], 1);
    qc[5] = __shfl_down_sync(0xFFFFFFFFu, qc[1], 1);
    qt[5] = __shfl_down_sync(0xFFFFFFFFu, qt[1], 1);
    qb[5] = __shfl_down_sync(0xFFFFFFFFu, qb[1], 1);

    if (lane == 0) {
        const bool hasLeft = (s != 0);
        qc[0] = hasLeft ? quant8(rowc[-1]) : 0.f;
        qt[0] = (hasLeft && hasTop) ? quant8(rowt[-1]) : 0.f;
        qb[0] = (hasLeft && hasBot) ? quant8(rowb[-1]) : 0.f;
    }
    if (lane == 31) {
        const bool hasRight = (s != 3);
        qc[5] = hasRight ? quant8(rowc[128]) : 0.f;
        qt[5] = (hasRight && hasTop) ? quant8(rowt[128]) : 0.f;
        qb[5] = (hasRight && hasBot) ? quant8(rowb[128]) : 0.f;
    }

    float res[4];
#pragma unroll
    for (int j = 0; j < 4; j++) {
        const float ctr = qc[j + 1];
        // circular neighbor order: tl, t, tr, r, br, b, bl, l
        unsigned m = 0;
        m |= (qt[j    ] >= ctr) ? 1u        : 0u;  // (-1,-1)
        m |= (qt[j + 1] >= ctr) ? (1u << 1) : 0u;  // (-1, 0)
        m |= (qt[j + 2] >= ctr) ? (1u << 2) : 0u;  // (-1, 1)
        m |= (qc[j + 2] >= ctr) ? (1u << 3) : 0u;  // ( 0, 1)
        m |= (qb[j + 2] >= ctr) ? (1u << 4) : 0u;  // ( 1, 1)
        m |= (qb[j + 1] >= ctr) ? (1u << 5) : 0u;  // ( 1, 0)
        m |= (qb[j    ] >= ctr) ? (1u << 6) : 0u;  // ( 1,-1)
        m |= (qc[j    ] >= ctr) ? (1u << 7) : 0u;  // ( 0,-1)
        const unsigned rot = ((m << 1) | (m >> 7)) & 0xFFu;
        const int trans = __popc(m ^ rot);
        const int ones  = __popc(m);
        const int lbp = (trans <= 2) ? ones : 9;
        res[j] = (float)lbp * (1.0f / 255.0f);
    }

    float4 o4 = make_float4(res[0], res[1], res[2], res[3]);
    *reinterpret_cast<float4*>(out + (size_t)r * IMG_W + s * 128 + col) = o4;
}

extern "C" void kernel_launch(void* const* d_in, const int* in_sizes, int n_in,
                              void* d_out, int out_size) {
    const float* x = (const float*)d_in[0];
    float* out = (float*)d_out;
    const int nrows = out_size / IMG_W;        // B*C*H
    const int nwarps = nrows * 4;              // 4 segments of 128 cols
    const int threads = 256;                   // 8 warps/block
    const int blocks = (nwarps + 7) / 8;
    lbp_kernel<<<blocks, threads>>>(x, out, nrows);
}

// round 2
// speedup vs baseline: 1.1024x; 1.1024x over previous
#include <cuda_runtime.h>
#include <cuda_bf16.h>

// LBP uniform (P=8, R=1) over (B,C,H,W)=(32,3,512,512) float32.
// out = (trans<=2 ? popcount(bits) : 9) / 255
// bits[i] = quant(neighbor_i) >= quant(center), zero-padded borders.
//
// R2: ALU-pipe was the bottleneck (79%). Two reductions:
//  (1) floor(u)>=floor(v) <=> u>=floor(v): only centers get floorf; neighbors
//      compare raw x*255 (exact fp32 compare, inputs in [0,1)).
//  (2) 256-entry shared-mem LUT replaces rot/xor/popc/popc/sel/cvt/mul tail.

#define IMG_W 512
#define IMG_H 512

__global__ __launch_bounds__(256)
void lbp_kernel(const float* __restrict__ x, float* __restrict__ out, int nrows) {
    __shared__ float lut[256];
    {
        const unsigned m = threadIdx.x & 255u;   // blockDim == 256
        const unsigned rot = ((m << 1) | (m >> 7)) & 0xFFu;
        const int trans = __popc(m ^ rot);
        const int ones  = __popc(m);
        lut[m] = (float)(trans <= 2 ? ones : 9) * (1.0f / 255.0f);
    }
    __syncthreads();

    const int warpG = blockIdx.x * (blockDim.x >> 5) + (threadIdx.x >> 5);
    const int lane  = threadIdx.x & 31;
    const int r = warpG >> 2;        // flattened row over B*C*H
    const int s = warpG & 3;         // which 128-col segment
    if (r >= nrows) return;

    const int h = r & (IMG_H - 1);   // row within image
    const bool hasTop = (h != 0);
    const bool hasBot = (h != IMG_H - 1);

    const float* rowc = x + (size_t)r * IMG_W + s * 128;
    const float* rowt = rowc - IMG_W;
    const float* rowb = rowc + IMG_W;
    const int col = lane * 4;

    const float4 z4 = make_float4(0.f, 0.f, 0.f, 0.f);
    float4 c4 = *reinterpret_cast<const float4*>(rowc + col);
    float4 t4 = hasTop ? *reinterpret_cast<const float4*>(rowt + col) : z4;
    float4 b4 = hasBot ? *reinterpret_cast<const float4*>(rowb + col) : z4;

    // raw scaled values (x*255), [0]=left halo, [1..4]=own cols, [5]=right halo
    float qc[6], qt[6], qb[6];
    qc[1] = c4.x * 255.0f; qc[2] = c4.y * 255.0f; qc[3] = c4.z * 255.0f; qc[4] = c4.w * 255.0f;
    qt[1] = t4.x * 255.0f; qt[2] = t4.y * 255.0f; qt[3] = t4.z * 255.0f; qt[4] = t4.w * 255.0f;
    qb[1] = b4.x * 255.0f; qb[2] = b4.y * 255.0f; qb[3] = b4.z * 255.0f; qb[4] = b4.w * 255.0f;

    // halo via shuffle (raw scaled values)
    qc[0] = __shfl_up_sync(0xFFFFFFFFu, qc[4], 1);
    qt[0] = __shfl_up_sync(0xFFFFFFFFu, qt[4], 1);
    qb[0] = __shfl_up_sync(0xFFFFFFFFu, qb[4], 1);
    qc[5] = __shfl_down_sync(0xFFFFFFFFu, qc[1], 1);
    qt[5] = __shfl_down_sync(0xFFFFFFFFu, qt[1], 1);
    qb[5] = __shfl_down_sync(0xFFFFFFFFu, qb[1], 1);

    if (lane == 0) {
        const bool hasLeft = (s != 0);
        qc[0] = hasLeft ? rowc[-1] * 255.0f : 0.f;
        qt[0] = (hasLeft && hasTop) ? rowt[-1] * 255.0f : 0.f;
        qb[0] = (hasLeft && hasBot) ? rowb[-1] * 255.0f : 0.f;
    }
    if (lane == 31) {
        const bool hasRight = (s != 3);
        qc[5] = hasRight ? rowc[128] * 255.0f : 0.f;
        qt[5] = (hasRight && hasTop) ? rowt[128] * 255.0f : 0.f;
        qb[5] = (hasRight && hasBot) ? rowb[128] * 255.0f : 0.f;
    }

    // only centers need the floor (floor(u)>=floor(v) <=> u>=floor(v))
    float fc[4];
    fc[0] = floorf(qc[1]); fc[1] = floorf(qc[2]);
    fc[2] = floorf(qc[3]); fc[3] = floorf(qc[4]);

    float res[4];
#pragma unroll
    for (int j = 0; j < 4; j++) {
        const float ctr = fc[j];
        // circular neighbor order: tl, t, tr, r, br, b, bl, l
        const unsigned m =
              (unsigned)(qt[j    ] >= ctr)
            | ((unsigned)(qt[j + 1] >= ctr) << 1)
            | ((unsigned)(qt[j + 2] >= ctr) << 2)
            | ((unsigned)(qc[j + 2] >= ctr) << 3)
            | ((unsigned)(qb[j + 2] >= ctr) << 4)
            | ((unsigned)(qb[j + 1] >= ctr) << 5)
            | ((unsigned)(qb[j    ] >= ctr) << 6)
            | ((unsigned)(qc[j    ] >= ctr) << 7);
        res[j] = lut[m];
    }

    float4 o4 = make_float4(res[0], res[1], res[2], res[3]);
    *reinterpret_cast<float4*>(out + (size_t)r * IMG_W + s * 128 + col) = o4;
}

extern "C" void kernel_launch(void* const* d_in, const int* in_sizes, int n_in,
                              void* d_out, int out_size) {
    const float* x = (const float*)d_in[0];
    float* out = (float*)d_out;
    const int nrows = out_size / IMG_W;        // B*C*H
    const int nwarps = nrows * 4;              // 4 segments of 128 cols
    const int threads = 256;                   // 8 warps/block
    const int blocks = (nwarps + 7) / 8;
    lbp_kernel<<<blocks, threads>>>(x, out, nrows);
}

// round 3
// speedup vs baseline: 1.3378x; 1.2136x over previous
#include <cuda_runtime.h>
#include <cuda_bf16.h>

// LBP uniform (P=8, R=1) over (B,C,H,W)=(32,3,512,512) float32.
// R3: move compare+merge from ALU pipe (was 62.6%) to FMA pipe (was 13%):
//   FSET (set.ge.f32.f32 -> 1.0f/0.0f) + FFMA-immediate accumulation chain,
//   then F2I + LDS LUT. 8 pixels/thread to amortize shuffles/addressing.

#define IMG_W 512
#define IMG_H 512

__device__ __forceinline__ float fset_ge(float a, float b) {
    float d;
    asm("set.ge.f32.f32 %0, %1, %2;" : "=f"(d) : "f"(a), "f"(b));
    return d;  // 1.0f if a>=b else 0.0f
}

__global__ __launch_bounds__(256)
void lbp_kernel(const float* __restrict__ x, float* __restrict__ out, int nrows) {
    __shared__ float lut[256];
    {
        const unsigned m = threadIdx.x & 255u;
        const unsigned rot = ((m << 1) | (m >> 7)) & 0xFFu;
        const int trans = __popc(m ^ rot);
        const int ones  = __popc(m);
        lut[m] = (float)(trans <= 2 ? ones : 9) * (1.0f / 255.0f);
    }
    __syncthreads();

    const int warpG = blockIdx.x * (blockDim.x >> 5) + (threadIdx.x >> 5);
    const int lane  = threadIdx.x & 31;
    const int r = warpG >> 1;        // flattened row over B*C*H
    const int s = warpG & 1;         // which 256-col segment
    if (r >= nrows) return;

    const int h = r & (IMG_H - 1);
    const bool hasTop = (h != 0);
    const bool hasBot = (h != IMG_H - 1);

    const float* rowc = x + (size_t)r * IMG_W + s * 256;
    const float* rowt = rowc - IMG_W;
    const float* rowb = rowc + IMG_W;
    const int col = lane * 8;

    const float4 z4 = make_float4(0.f, 0.f, 0.f, 0.f);
    float4 c4a = *reinterpret_cast<const float4*>(rowc + col);
    float4 c4b = *reinterpret_cast<const float4*>(rowc + col + 4);
    float4 t4a = hasTop ? *reinterpret_cast<const float4*>(rowt + col)     : z4;
    float4 t4b = hasTop ? *reinterpret_cast<const float4*>(rowt + col + 4) : z4;
    float4 b4a = hasBot ? *reinterpret_cast<const float4*>(rowb + col)     : z4;
    float4 b4b = hasBot ? *reinterpret_cast<const float4*>(rowb + col + 4) : z4;

    // scaled values (x*255): [0]=left halo, [1..8]=own, [9]=right halo
    float qc[10], qt[10], qb[10];
    qc[1]=c4a.x*255.f; qc[2]=c4a.y*255.f; qc[3]=c4a.z*255.f; qc[4]=c4a.w*255.f;
    qc[5]=c4b.x*255.f; qc[6]=c4b.y*255.f; qc[7]=c4b.z*255.f; qc[8]=c4b.w*255.f;
    qt[1]=t4a.x*255.f; qt[2]=t4a.y*255.f; qt[3]=t4a.z*255.f; qt[4]=t4a.w*255.f;
    qt[5]=t4b.x*255.f; qt[6]=t4b.y*255.f; qt[7]=t4b.z*255.f; qt[8]=t4b.w*255.f;
    qb[1]=b4a.x*255.f; qb[2]=b4a.y*255.f; qb[3]=b4a.z*255.f; qb[4]=b4a.w*255.f;
    qb[5]=b4b.x*255.f; qb[6]=b4b.y*255.f; qb[7]=b4b.z*255.f; qb[8]=b4b.w*255.f;

    qc[0] = __shfl_up_sync(0xFFFFFFFFu, qc[8], 1);
    qt[0] = __shfl_up_sync(0xFFFFFFFFu, qt[8], 1);
    qb[0] = __shfl_up_sync(0xFFFFFFFFu, qb[8], 1);
    qc[9] = __shfl_down_sync(0xFFFFFFFFu, qc[1], 1);
    qt[9] = __shfl_down_sync(0xFFFFFFFFu, qt[1], 1);
    qb[9] = __shfl_down_sync(0xFFFFFFFFu, qb[1], 1);

    if (lane == 0) {
        const bool hasLeft = (s != 0);
        qc[0] = hasLeft ? rowc[-1] * 255.f : 0.f;
        qt[0] = (hasLeft && hasTop) ? rowt[-1] * 255.f : 0.f;
        qb[0] = (hasLeft && hasBot) ? rowb[-1] * 255.f : 0.f;
    }
    if (lane == 31) {
        const bool hasRight = (s != 1);
        qc[9] = hasRight ? rowc[256] * 255.f : 0.f;
        qt[9] = (hasRight && hasTop) ? rowt[256] * 255.f : 0.f;
        qb[9] = (hasRight && hasBot) ? rowb[256] * 255.f : 0.f;
    }

    float res[8];
#pragma unroll
    for (int j = 0; j < 8; j++) {
        const float ctr = floorf(qc[j + 1]);  // only centers need floor
        // circular order: tl, t, tr, r, br, b, bl, l  (bits 0..7)
        float m;
        m = fset_ge(qt[j    ], ctr);                        // bit 0
        m = fmaf(fset_ge(qt[j + 1], ctr),   2.0f, m);       // bit 1
        m = fmaf(fset_ge(qt[j + 2], ctr),   4.0f, m);       // bit 2
        m = fmaf(fset_ge(qc[j + 2], ctr),   8.0f, m);       // bit 3
        m = fmaf(fset_ge(qb[j + 2], ctr),  16.0f, m);       // bit 4
        m = fmaf(fset_ge(qb[j + 1], ctr),  32.0f, m);       // bit 5
        m = fmaf(fset_ge(qb[j    ], ctr),  64.0f, m);       // bit 6
        m = fmaf(fset_ge(qc[j    ], ctr), 128.0f, m);       // bit 7
        res[j] = lut[(int)m];
    }

    float* op = out + (size_t)r * IMG_W + s * 256 + col;
    *reinterpret_cast<float4*>(op)     = make_float4(res[0], res[1], res[2], res[3]);
    *reinterpret_cast<float4*>(op + 4) = make_float4(res[4], res[5], res[6], res[7]);
}

extern "C" void kernel_launch(void* const* d_in, const int* in_sizes, int n_in,
                              void* d_out, int out_size) {
    const float* x = (const float*)d_in[0];
    float* out = (float*)d_out;
    const int nrows = out_size / IMG_W;     // B*C*H
    const int nwarps = nrows * 2;           // 2 segments of 256 cols
    const int threads = 256;                // 8 warps/block
    const int blocks = (nwarps + 7) / 8;
    lbp_kernel<<<blocks, threads>>>(x, out, nrows);
}

// round 4
// speedup vs baseline: 1.4128x; 1.0560x over previous
#include <cuda_runtime.h>
#include <cuda_bf16.h>

// LBP uniform (P=8, R=1) over (B,C,H,W)=(32,3,512,512) float32.
// R4: L1TEX was the ceiling (78.9%) — the bank-conflicted shared-mem LUT cost
// as many L1 wavefronts as the real memory traffic. Replace LDS LUT with a
// pure-arithmetic tail (rot/xor/popc/popc/sel on ALU pipe, which has headroom).
// No shared memory at all now.

#define IMG_W 512
#define IMG_H 512

__device__ __forceinline__ float fset_ge(float a, float b) {
    float d;
    asm("set.ge.f32.f32 %0, %1, %2;" : "=f"(d) : "f"(a), "f"(b));
    return d;  // 1.0f if a>=b else 0.0f
}

__global__ __launch_bounds__(256)
void lbp_kernel(const float* __restrict__ x, float* __restrict__ out, int nrows) {
    const int warpG = blockIdx.x * (blockDim.x >> 5) + (threadIdx.x >> 5);
    const int lane  = threadIdx.x & 31;
    const int r = warpG >> 1;        // flattened row over B*C*H
    const int s = warpG & 1;         // which 256-col segment
    if (r >= nrows) return;

    const int h = r & (IMG_H - 1);
    const bool hasTop = (h != 0);
    const bool hasBot = (h != IMG_H - 1);

    const float* rowc = x + (size_t)r * IMG_W + s * 256;
    const float* rowt = rowc - IMG_W;
    const float* rowb = rowc + IMG_W;
    const int col = lane * 8;

    const float4 z4 = make_float4(0.f, 0.f, 0.f, 0.f);
    float4 c4a = *reinterpret_cast<const float4*>(rowc + col);
    float4 c4b = *reinterpret_cast<const float4*>(rowc + col + 4);
    float4 t4a = hasTop ? *reinterpret_cast<const float4*>(rowt + col)     : z4;
    float4 t4b = hasTop ? *reinterpret_cast<const float4*>(rowt + col + 4) : z4;
    float4 b4a = hasBot ? *reinterpret_cast<const float4*>(rowb + col)     : z4;
    float4 b4b = hasBot ? *reinterpret_cast<const float4*>(rowb + col + 4) : z4;

    // scaled values (x*255): [0]=left halo, [1..8]=own, [9]=right halo
    float qc[10], qt[10], qb[10];
    qc[1]=c4a.x*255.f; qc[2]=c4a.y*255.f; qc[3]=c4a.z*255.f; qc[4]=c4a.w*255.f;
    qc[5]=c4b.x*255.f; qc[6]=c4b.y*255.f; qc[7]=c4b.z*255.f; qc[8]=c4b.w*255.f;
    qt[1]=t4a.x*255.f; qt[2]=t4a.y*255.f; qt[3]=t4a.z*255.f; qt[4]=t4a.w*255.f;
    qt[5]=t4b.x*255.f; qt[6]=t4b.y*255.f; qt[7]=t4b.z*255.f; qt[8]=t4b.w*255.f;
    qb[1]=b4a.x*255.f; qb[2]=b4a.y*255.f; qb[3]=b4a.z*255.f; qb[4]=b4a.w*255.f;
    qb[5]=b4b.x*255.f; qb[6]=b4b.y*255.f; qb[7]=b4b.z*255.f; qb[8]=b4b.w*255.f;

    qc[0] = __shfl_up_sync(0xFFFFFFFFu, qc[8], 1);
    qt[0] = __shfl_up_sync(0xFFFFFFFFu, qt[8], 1);
    qb[0] = __shfl_up_sync(0xFFFFFFFFu, qb[8], 1);
    qc[9] = __shfl_down_sync(0xFFFFFFFFu, qc[1], 1);
    qt[9] = __shfl_down_sync(0xFFFFFFFFu, qt[1], 1);
    qb[9] = __shfl_down_sync(0xFFFFFFFFu, qb[1], 1);

    if (lane == 0) {
        const bool hasLeft = (s != 0);
        qc[0] = hasLeft ? rowc[-1] * 255.f : 0.f;
        qt[0] = (hasLeft && hasTop) ? rowt[-1] * 255.f : 0.f;
        qb[0] = (hasLeft && hasBot) ? rowb[-1] * 255.f : 0.f;
    }
    if (lane == 31) {
        const bool hasRight = (s != 1);
        qc[9] = hasRight ? rowc[256] * 255.f : 0.f;
        qt[9] = (hasRight && hasTop) ? rowt[256] * 255.f : 0.f;
        qb[9] = (hasRight && hasBot) ? rowb[256] * 255.f : 0.f;
    }

    float res[8];
#pragma unroll
    for (int j = 0; j < 8; j++) {
        const float ctr = floorf(qc[j + 1]);  // only centers need floor
        // circular order: tl, t, tr, r, br, b, bl, l  (bits 0..7)
        float m;
        m = fset_ge(qt[j    ], ctr);                        // bit 0
        m = fmaf(fset_ge(qt[j + 1], ctr),   2.0f, m);       // bit 1
        m = fmaf(fset_ge(qt[j + 2], ctr),   4.0f, m);       // bit 2
        m = fmaf(fset_ge(qc[j + 2], ctr),   8.0f, m);       // bit 3
        m = fmaf(fset_ge(qb[j + 2], ctr),  16.0f, m);       // bit 4
        m = fmaf(fset_ge(qb[j + 1], ctr),  32.0f, m);       // bit 5
        m = fmaf(fset_ge(qb[j    ], ctr),  64.0f, m);       // bit 6
        m = fmaf(fset_ge(qc[j    ], ctr), 128.0f, m);       // bit 7
        const unsigned mi  = (unsigned)(int)m;
        const unsigned rot = ((mi << 1) | (mi >> 7)) & 0xFFu;
        const int trans = __popc(mi ^ rot);
        const int ones  = __popc(mi);
        const int lbp   = (trans <= 2) ? ones : 9;
        res[j] = (float)lbp * (1.0f / 255.0f);
    }

    float* op = out + (size_t)r * IMG_W + s * 256 + col;
    *reinterpret_cast<float4*>(op)     = make_float4(res[0], res[1], res[2], res[3]);
    *reinterpret_cast<float4*>(op + 4) = make_float4(res[4], res[5], res[6], res[7]);
}

extern "C" void kernel_launch(void* const* d_in, const int* in_sizes, int n_in,
                              void* d_out, int out_size) {
    const float* x = (const float*)d_in[0];
    float* out = (float*)d_out;
    const int nrows = out_size / IMG_W;     // B*C*H
    const int nwarps = nrows * 2;           // 2 segments of 256 cols
    const int threads = 256;                // 8 warps/block
    const int blocks = (nwarps + 7) / 8;
    lbp_kernel<<<blocks, threads>>>(x, out, nrows);
}